// round 7
// baseline (speedup 1.0000x reference)
#include <cuda_runtime.h>
#include <cuda_fp16.h>
#include <math.h>
#include <float.h>

#define NN 100000
#define EE 1600000
#define HH 64
#define CC 10
#define SCAN_BLK 1024
#define SCAN_NBLK ((NN + SCAN_BLK - 1) / SCAN_BLK)   // 98

#define AS_STRIDE 68
#define WS_STRIDE 72
#define GSMEM ((2 * 64 * AS_STRIDE + 2 * 64 * WS_STRIDE) * 4)   // 71680 B

// ---------------- static device scratch ----------------
__device__ int          g_dst[EE];
__device__ int          g_col[EE];
__device__ int          g_deg[NN];
__device__ int          g_rowptr[NN + 1];
__device__ int          g_cursor[NN];
__device__ int          g_blocksum[SCAN_NBLK];
__device__ float        g_h[NN * HH];        // fp32 node features
__device__ unsigned int g_hh[NN * 32];       // fp16x2 shadow copy
__device__ float        g_agg[NN * HH];      // segment-max result (fp32)
__device__ int          g_odd_nonzero;

__device__ __forceinline__ float tf32_rn(float x) {
    unsigned r;
    asm("cvt.rna.tf32.f32 %0, %1;" : "=r"(r) : "f"(x));
    return __uint_as_float(r);
}

__device__ __forceinline__ void mma_tf32(float c[4], const unsigned a[4],
                                         unsigned b0, unsigned b1) {
    asm("mma.sync.aligned.m16n8k8.row.col.f32.tf32.tf32.f32 "
        "{%0,%1,%2,%3}, {%4,%5,%6,%7}, {%8,%9}, {%0,%1,%2,%3};"
        : "+f"(c[0]), "+f"(c[1]), "+f"(c[2]), "+f"(c[3])
        : "r"(a[0]), "r"(a[1]), "r"(a[2]), "r"(a[3]), "r"(b0), "r"(b1));
}

// ---------------- setup: zero degrees + edge dtype detection ----------------
// int64 edge ids < 2^31 -> every odd 32-bit word is 0.
__global__ void zerodetect_kernel(const unsigned int* __restrict__ w) {
    int i = blockIdx.x * blockDim.x + threadIdx.x;
    if (i < NN) g_deg[i] = 0;
    if (i == 0) g_odd_nonzero = 0;
    if (i < 65536) {
        unsigned int v = w[2 * i + 1];
        if (v) atomicOr(&g_odd_nonzero, 1);
    }
}

__global__ void convert_kernel(const void* __restrict__ ei) {
    int i = blockIdx.x * blockDim.x + threadIdx.x;
    if (i >= EE) return;
    int d;
    if (g_odd_nonzero == 0) d = (int)((const long long*)ei)[EE + i];
    else                    d = ((const int*)ei)[EE + i];
    g_dst[i] = d;
    atomicAdd(&g_deg[d], 1);
}

// ---------------- multi-block exclusive scan ----------------
__global__ void scan_phase1() {
    __shared__ int warp_sums[32];
    int tid = threadIdx.x;
    int i = blockIdx.x * SCAN_BLK + tid;
    int v = (i < NN) ? g_deg[i] : 0;
    int lane = tid & 31, wid = tid >> 5;

    int incl = v;
#pragma unroll
    for (int off = 1; off < 32; off <<= 1) {
        int t = __shfl_up_sync(0xffffffffu, incl, off);
        if (lane >= off) incl += t;
    }
    if (lane == 31) warp_sums[wid] = incl;
    __syncthreads();
    if (wid == 0) {
        int ws = warp_sums[lane];
        int wincl = ws;
#pragma unroll
        for (int off = 1; off < 32; off <<= 1) {
            int t = __shfl_up_sync(0xffffffffu, wincl, off);
            if (lane >= off) wincl += t;
        }
        warp_sums[lane] = wincl - ws;
        if (lane == 31) g_blocksum[blockIdx.x] = wincl;
    }
    __syncthreads();
    int excl = incl - v + warp_sums[wid];
    if (i < NN) g_rowptr[i] = excl;
}

__global__ void scan_phase2() {
    __shared__ int ws4[4];
    __shared__ int total;
    int tid = threadIdx.x;            // 128 threads
    int v = (tid < SCAN_NBLK) ? g_blocksum[tid] : 0;
    int lane = tid & 31, wid = tid >> 5;
    int incl = v;
#pragma unroll
    for (int off = 1; off < 32; off <<= 1) {
        int t = __shfl_up_sync(0xffffffffu, incl, off);
        if (lane >= off) incl += t;
    }
    if (lane == 31) ws4[wid] = incl;
    __syncthreads();
    if (tid == 0) {
        int c = 0;
        for (int w = 0; w < 4; w++) { int t = ws4[w]; ws4[w] = c; c += t; }
        total = c;
    }
    __syncthreads();
    if (tid < SCAN_NBLK) g_blocksum[tid] = incl - v + ws4[wid];
    if (tid == 0) g_rowptr[NN] = total;
}

__global__ void scan_phase3() {
    int i = blockIdx.x * SCAN_BLK + threadIdx.x;
    if (i >= NN) return;
    int r = g_rowptr[i] + g_blocksum[blockIdx.x];
    g_rowptr[i] = r;
    g_cursor[i] = r;
}

__global__ void scatter_kernel(const void* __restrict__ ei) {
    int i = blockIdx.x * blockDim.x + threadIdx.x;
    if (i >= EE) return;
    int s;
    if (g_odd_nonzero == 0) s = (int)((const long long*)ei)[i];
    else                    s = ((const int*)ei)[i];
    int d = g_dst[i];
    int pos = atomicAdd(&g_cursor[d], 1);
    g_col[pos] = s;
}

// ---------------- segment max over fp16 shadow: one warp per node ----------------
__global__ void segmax_kernel() {
    int gw   = (blockIdx.x * blockDim.x + threadIdx.x) >> 5;
    int lane = threadIdx.x & 31;
    if (gw >= NN) return;
    int beg = g_rowptr[gw], end = g_rowptr[gw + 1];
    __half2 hacc = __floats2half2_rn(-65504.f, -65504.f);
    for (int base = beg; base < end; base += 32) {
        int cnt = min(32, end - base);
        int s = 0;
        if (lane < cnt) s = g_col[base + lane];
        for (int e = 0; e < cnt; e++) {
            int sv = __shfl_sync(0xffffffffu, s, e);
            unsigned int pv = g_hh[sv * 32 + lane];
            hacc = __hmax2(hacc, *(__half2*)&pv);
        }
    }
    float2 m = __half22float2(hacc);
    if (beg == end) { m.x = 0.f; m.y = 0.f; }
    ((float2*)g_agg)[gw * 32 + lane] = m;
}

// ---------------- 64x64 GEMM via 3xTF32 tensor-core MMA ----------------
// C = (A [+ A2]) @ W + b, fp32-accurate via hi/lo split (error ~2^-24).
// 256 threads = 8 warps: warp (wid&3) owns m-rows 16*(wid&3).., (wid>>2)
// owns n-cols 32*(wid>>2)..  Also emits fp16 shadow copy.
template <bool ADD>
__global__ void __launch_bounds__(256)
gemm_tf32_kernel(const float* __restrict__ A,
                 const float* __restrict__ A2,
                 const float* __restrict__ W,
                 const float* __restrict__ bias,
                 float* __restrict__ Cm,
                 unsigned int* __restrict__ Ch, int n) {
    extern __shared__ float sm[];
    float* AsHi = sm;                            // [64][AS_STRIDE]
    float* AsLo = AsHi + 64 * AS_STRIDE;
    float* WsHi = AsLo + 64 * AS_STRIDE;         // [k][WS_STRIDE]
    float* WsLo = WsHi + 64 * WS_STRIDE;

    int tid = threadIdx.x;
    int block_row = blockIdx.x * 64;

    // stage W split (k-major rows of n)
    for (int i = tid; i < 1024; i += 256) {
        int k = i >> 4, j4 = i & 15;
        float4 v = ((const float4*)W)[i];
        float4 hi, lo;
        hi.x = tf32_rn(v.x); lo.x = tf32_rn(v.x - hi.x);
        hi.y = tf32_rn(v.y); lo.y = tf32_rn(v.y - hi.y);
        hi.z = tf32_rn(v.z); lo.z = tf32_rn(v.z - hi.z);
        hi.w = tf32_rn(v.w); lo.w = tf32_rn(v.w - hi.w);
        *(float4*)&WsHi[k * WS_STRIDE + j4 * 4] = hi;
        *(float4*)&WsLo[k * WS_STRIDE + j4 * 4] = lo;
    }
    // stage A (+A2) split (row-major)
    for (int i = tid; i < 1024; i += 256) {
        int m = i >> 4, k4 = i & 15;
        int row = block_row + m;
        float4 v = make_float4(0.f, 0.f, 0.f, 0.f);
        if (row < n) {
            v = ((const float4*)A)[row * 16 + k4];
            if (ADD) {
                float4 u = ((const float4*)A2)[row * 16 + k4];
                v.x += u.x; v.y += u.y; v.z += u.z; v.w += u.w;
            }
        }
        float4 hi, lo;
        hi.x = tf32_rn(v.x); lo.x = tf32_rn(v.x - hi.x);
        hi.y = tf32_rn(v.y); lo.y = tf32_rn(v.y - hi.y);
        hi.z = tf32_rn(v.z); lo.z = tf32_rn(v.z - hi.z);
        hi.w = tf32_rn(v.w); lo.w = tf32_rn(v.w - hi.w);
        *(float4*)&AsHi[m * AS_STRIDE + k4 * 4] = hi;
        *(float4*)&AsLo[m * AS_STRIDE + k4 * 4] = lo;
    }
    __syncthreads();

    int lane = tid & 31, wid = tid >> 5;
    int gid = lane >> 2, tig = lane & 3;
    int m0 = (wid & 3) * 16;
    int n0 = (wid >> 2) * 32;

    float c[4][4];
#pragma unroll
    for (int i = 0; i < 4; i++)
#pragma unroll
        for (int j = 0; j < 4; j++) c[i][j] = 0.f;

#pragma unroll
    for (int ks = 0; ks < 8; ks++) {
        int k0 = ks * 8;
        int ra0 = (m0 + gid) * AS_STRIDE + k0 + tig;
        int ra1 = (m0 + gid + 8) * AS_STRIDE + k0 + tig;
        unsigned ahi[4], alo[4];
        ahi[0] = __float_as_uint(AsHi[ra0]);
        ahi[1] = __float_as_uint(AsHi[ra1]);
        ahi[2] = __float_as_uint(AsHi[ra0 + 4]);
        ahi[3] = __float_as_uint(AsHi[ra1 + 4]);
        alo[0] = __float_as_uint(AsLo[ra0]);
        alo[1] = __float_as_uint(AsLo[ra1]);
        alo[2] = __float_as_uint(AsLo[ra0 + 4]);
        alo[3] = __float_as_uint(AsLo[ra1 + 4]);
        int rb0 = (k0 + tig) * WS_STRIDE;
        int rb1 = (k0 + tig + 4) * WS_STRIDE;
#pragma unroll
        for (int nsub = 0; nsub < 4; nsub++) {
            int col = n0 + nsub * 8 + gid;
            unsigned bhi0 = __float_as_uint(WsHi[rb0 + col]);
            unsigned bhi1 = __float_as_uint(WsHi[rb1 + col]);
            unsigned blo0 = __float_as_uint(WsLo[rb0 + col]);
            unsigned blo1 = __float_as_uint(WsLo[rb1 + col]);
            mma_tf32(c[nsub], ahi, bhi0, bhi1);
            mma_tf32(c[nsub], ahi, blo0, blo1);
            mma_tf32(c[nsub], alo, bhi0, bhi1);
        }
    }

    // epilogue: bias + fp32 store + fp16 shadow
#pragma unroll
    for (int nsub = 0; nsub < 4; nsub++) {
        int col = n0 + nsub * 8 + 2 * tig;
        float2 bb = *(const float2*)&bias[col];
        int r0 = block_row + m0 + gid;
        int r1 = r0 + 8;
        if (r0 < n) {
            float2 o = make_float2(c[nsub][0] + bb.x, c[nsub][1] + bb.y);
            *(float2*)&Cm[r0 * 64 + col] = o;
            __half2 p = __floats2half2_rn(o.x, o.y);
            Ch[r0 * 32 + (col >> 1)] = *(unsigned*)&p;
        }
        if (r1 < n) {
            float2 o = make_float2(c[nsub][2] + bb.x, c[nsub][3] + bb.y);
            *(float2*)&Cm[r1 * 64 + col] = o;
            __half2 p = __floats2half2_rn(o.x, o.y);
            Ch[r1 * 32 + (col >> 1)] = *(unsigned*)&p;
        }
    }
}

// ---------------- decoder + log-softmax ----------------
__global__ void decoder_kernel(const float* __restrict__ dw,
                               const float* __restrict__ db,
                               float* __restrict__ out, int n) {
    __shared__ float Ws[HH * CC];
    __shared__ float bs[CC];
    int tid = threadIdx.x;
    for (int i = tid; i < HH * CC; i += blockDim.x) Ws[i] = dw[i];
    if (tid < CC) bs[tid] = db[tid];
    __syncthreads();
    int node = blockIdx.x * blockDim.x + tid;
    if (node >= n) return;
    float acc[CC];
#pragma unroll
    for (int c = 0; c < CC; c++) acc[c] = bs[c];
    const float4* hp = (const float4*)(g_h + node * HH);
#pragma unroll
    for (int k4 = 0; k4 < 16; k4++) {
        float4 v = hp[k4];
        int kb = k4 * 4;
#pragma unroll
        for (int c = 0; c < CC; c++)
            acc[c] += v.x * Ws[(kb + 0) * CC + c] + v.y * Ws[(kb + 1) * CC + c] +
                      v.z * Ws[(kb + 2) * CC + c] + v.w * Ws[(kb + 3) * CC + c];
    }
    float mx = acc[0];
#pragma unroll
    for (int c = 1; c < CC; c++) mx = fmaxf(mx, acc[c]);
    float s = 0.f;
#pragma unroll
    for (int c = 0; c < CC; c++) s += expf(acc[c] - mx);
    float lse = mx + logf(s);
#pragma unroll
    for (int c = 0; c < CC; c++) out[node * CC + c] = acc[c] - lse;
}

// ---------------- launch ----------------
extern "C" void kernel_launch(void* const* d_in, const int* in_sizes, int n_in,
                              void* d_out, int out_size) {
    const float* x      = (const float*)d_in[0];
    const void*  ei     = d_in[1];
    const float* enc_w  = (const float*)d_in[3];
    const float* enc_b  = (const float*)d_in[4];
    const float* proc_w = (const float*)d_in[5];
    const float* proc_b = (const float*)d_in[6];
    const float* dec_w  = (const float*)d_in[7];
    const float* dec_b  = (const float*)d_in[8];
    float* out = (float*)d_out;

    float* hptr = nullptr;
    float* aggptr = nullptr;
    unsigned int* hhptr = nullptr;
    cudaGetSymbolAddress((void**)&hptr, g_h);
    cudaGetSymbolAddress((void**)&aggptr, g_agg);
    cudaGetSymbolAddress((void**)&hhptr, g_hh);

    cudaFuncSetAttribute(gemm_tf32_kernel<false>,
                         cudaFuncAttributeMaxDynamicSharedMemorySize, GSMEM);
    cudaFuncSetAttribute(gemm_tf32_kernel<true>,
                         cudaFuncAttributeMaxDynamicSharedMemorySize, GSMEM);

    const int n = NN;
    const int ggrid = (n + 63) / 64;

    // fork: encoder GEMM runs concurrently with CSR build
    cudaStream_t s2;
    cudaStreamCreateWithFlags(&s2, cudaStreamNonBlocking);
    cudaEvent_t e0, e1;
    cudaEventCreateWithFlags(&e0, cudaEventDisableTiming);
    cudaEventCreateWithFlags(&e1, cudaEventDisableTiming);
    cudaEventRecord(e0, 0);
    cudaStreamWaitEvent(s2, e0, 0);

    // encoder on s2 (emits fp32 h + fp16 shadow)
    gemm_tf32_kernel<false><<<ggrid, 256, GSMEM, s2>>>(x, nullptr, enc_w, enc_b,
                                                       hptr, hhptr, n);
    cudaEventRecord(e1, s2);

    // CSR build on capture stream
    zerodetect_kernel<<<(NN + 255) / 256, 256>>>((const unsigned int*)ei);
    convert_kernel<<<(EE + 255) / 256, 256>>>(ei);
    scan_phase1<<<SCAN_NBLK, SCAN_BLK>>>();
    scan_phase2<<<1, 128>>>();
    scan_phase3<<<SCAN_NBLK, SCAN_BLK>>>();
    scatter_kernel<<<(EE + 255) / 256, 256>>>(ei);

    // join: need both CSR and encoder before first segmax
    cudaStreamWaitEvent(0, e1, 0);

    // 6 GIN layers
    for (int it = 0; it < 6; it++) {
        segmax_kernel<<<(NN * 32 + 255) / 256, 256>>>();
        gemm_tf32_kernel<true><<<ggrid, 256, GSMEM>>>(hptr, aggptr, proc_w, proc_b,
                                                      hptr, hhptr, n);
    }

    // decoder + log-softmax
    decoder_kernel<<<(n + 127) / 128, 128>>>(dec_w, dec_b, out, n);
}

// round 8
// speedup vs baseline: 1.0341x; 1.0341x over previous
#include <cuda_runtime.h>
#include <cuda_fp16.h>
#include <math.h>
#include <float.h>

#define NN 100000
#define EE 1600000
#define HH 64
#define CC 10
#define SCAN_BLK 1024
#define SCAN_NBLK ((NN + SCAN_BLK - 1) / SCAN_BLK)   // 98

// ---------------- static device scratch ----------------
__device__ int          g_dst[EE];
__device__ int          g_col[EE];
__device__ int          g_deg[NN];
__device__ int          g_rowptr[NN + 1];
__device__ int          g_cursor[NN];
__device__ int          g_blocksum[SCAN_NBLK];
__device__ float        g_h[NN * HH];        // fp32 node features
__device__ unsigned int g_hh[NN * 32];       // fp16x2 shadow copy
__device__ float        g_agg[NN * HH];      // segment-max result (fp32)
__device__ int          g_odd_nonzero;

// ---------------- setup: zero degrees + edge dtype detection ----------------
// int64 edge ids < 2^31 -> every odd 32-bit word is 0.
__global__ void zerodetect_kernel(const unsigned int* __restrict__ w) {
    int i = blockIdx.x * blockDim.x + threadIdx.x;
    if (i < NN) g_deg[i] = 0;
    if (i == 0) g_odd_nonzero = 0;
    if (i < 65536) {
        unsigned int v = w[2 * i + 1];
        if (v) atomicOr(&g_odd_nonzero, 1);
    }
}

__global__ void convert_kernel(const void* __restrict__ ei) {
    int i = blockIdx.x * blockDim.x + threadIdx.x;
    if (i >= EE) return;
    int d;
    if (g_odd_nonzero == 0) d = (int)((const long long*)ei)[EE + i];
    else                    d = ((const int*)ei)[EE + i];
    g_dst[i] = d;
    atomicAdd(&g_deg[d], 1);
}

// ---------------- multi-block exclusive scan ----------------
__global__ void scan_phase1() {
    __shared__ int warp_sums[32];
    int tid = threadIdx.x;
    int i = blockIdx.x * SCAN_BLK + tid;
    int v = (i < NN) ? g_deg[i] : 0;
    int lane = tid & 31, wid = tid >> 5;

    int incl = v;
#pragma unroll
    for (int off = 1; off < 32; off <<= 1) {
        int t = __shfl_up_sync(0xffffffffu, incl, off);
        if (lane >= off) incl += t;
    }
    if (lane == 31) warp_sums[wid] = incl;
    __syncthreads();
    if (wid == 0) {
        int ws = warp_sums[lane];
        int wincl = ws;
#pragma unroll
        for (int off = 1; off < 32; off <<= 1) {
            int t = __shfl_up_sync(0xffffffffu, wincl, off);
            if (lane >= off) wincl += t;
        }
        warp_sums[lane] = wincl - ws;
        if (lane == 31) g_blocksum[blockIdx.x] = wincl;
    }
    __syncthreads();
    int excl = incl - v + warp_sums[wid];
    if (i < NN) g_rowptr[i] = excl;
}

__global__ void scan_phase2() {
    __shared__ int ws4[4];
    __shared__ int total;
    int tid = threadIdx.x;            // 128 threads
    int v = (tid < SCAN_NBLK) ? g_blocksum[tid] : 0;
    int lane = tid & 31, wid = tid >> 5;
    int incl = v;
#pragma unroll
    for (int off = 1; off < 32; off <<= 1) {
        int t = __shfl_up_sync(0xffffffffu, incl, off);
        if (lane >= off) incl += t;
    }
    if (lane == 31) ws4[wid] = incl;
    __syncthreads();
    if (tid == 0) {
        int c = 0;
        for (int w = 0; w < 4; w++) { int t = ws4[w]; ws4[w] = c; c += t; }
        total = c;
    }
    __syncthreads();
    if (tid < SCAN_NBLK) g_blocksum[tid] = incl - v + ws4[wid];
    if (tid == 0) g_rowptr[NN] = total;
}

__global__ void scan_phase3() {
    int i = blockIdx.x * SCAN_BLK + threadIdx.x;
    if (i >= NN) return;
    int r = g_rowptr[i] + g_blocksum[blockIdx.x];
    g_rowptr[i] = r;
    g_cursor[i] = r;
}

__global__ void scatter_kernel(const void* __restrict__ ei) {
    int i = blockIdx.x * blockDim.x + threadIdx.x;
    if (i >= EE) return;
    int s;
    if (g_odd_nonzero == 0) s = (int)((const long long*)ei)[i];
    else                    s = ((const int*)ei)[i];
    int d = g_dst[i];
    int pos = atomicAdd(&g_cursor[d], 1);
    g_col[pos] = s;
}

// ---------------- segment max over fp16 shadow: 2 nodes per warp ----------------
// Two independent gather chains per warp double the outstanding-load MLP and
// halve per-node loop overhead. Lane owns one half2 (128B/edge coalesced).
__global__ void segmax_kernel() {
    int gw   = (blockIdx.x * blockDim.x + threadIdx.x) >> 5;
    int lane = threadIdx.x & 31;
    int n0 = gw * 2, n1 = gw * 2 + 1;
    if (n0 >= NN) return;
    int beg0 = g_rowptr[n0], end0 = g_rowptr[n0 + 1];
    int beg1, end1;
    if (n1 < NN) { beg1 = g_rowptr[n1]; end1 = g_rowptr[n1 + 1]; }
    else         { beg1 = 0; end1 = 0; }

    __half2 a0 = __floats2half2_rn(-65504.f, -65504.f);
    __half2 a1 = a0;
    int b0 = beg0, b1 = beg1;
    while (b0 < end0 || b1 < end1) {
        int c0 = min(32, end0 - b0);        // may be <= 0
        int c1 = min(32, end1 - b1);
        int s0 = 0, s1 = 0;
        if (lane < c0) s0 = g_col[b0 + lane];
        if (lane < c1) s1 = g_col[b1 + lane];
        int cm = max(c0, c1);
        for (int e = 0; e < cm; e++) {
            int v0 = __shfl_sync(0xffffffffu, s0, e);
            int v1 = __shfl_sync(0xffffffffu, s1, e);
            if (e < c0) {
                unsigned p = g_hh[v0 * 32 + lane];
                a0 = __hmax2(a0, *(__half2*)&p);
            }
            if (e < c1) {
                unsigned p = g_hh[v1 * 32 + lane];
                a1 = __hmax2(a1, *(__half2*)&p);
            }
        }
        b0 += 32; b1 += 32;
    }

    float2 m0 = __half22float2(a0);
    if (beg0 == end0) { m0.x = 0.f; m0.y = 0.f; }
    ((float2*)g_agg)[n0 * 32 + lane] = m0;
    if (n1 < NN) {
        float2 m1 = __half22float2(a1);
        if (beg1 == end1) { m1.x = 0.f; m1.y = 0.f; }
        ((float2*)g_agg)[n1 * 32 + lane] = m1;
    }
}

// ---------------- 64-wide fp32 GEMM: C = (A [+ A2]) @ W + b ----------------
// Also emits a packed fp16 shadow copy of C for the next layer's gather.
template <bool ADD>
__global__ void gemm64_kernel(const float* __restrict__ A,
                              const float* __restrict__ A2,
                              const float* __restrict__ W,
                              const float* __restrict__ bias,
                              float* __restrict__ Cm,
                              unsigned int* __restrict__ Ch, int n) {
    __shared__ float As[64][68];
    __shared__ float Ws[64][68];
    int tid = threadIdx.x;
    int block_row = blockIdx.x * 64;

    for (int i = tid; i < 1024; i += 256) {
        int k = i >> 4, j4 = i & 15;
        float4 v = ((const float4*)W)[i];
        *(float4*)&Ws[k][j4 * 4] = v;
    }
    for (int i = tid; i < 1024; i += 256) {
        int m = i >> 4, k4 = i & 15;
        int row = block_row + m;
        float4 v = make_float4(0.f, 0.f, 0.f, 0.f);
        if (row < n) {
            v = ((const float4*)A)[row * 16 + k4];
            if (ADD) {
                float4 u = ((const float4*)A2)[row * 16 + k4];
                v.x += u.x; v.y += u.y; v.z += u.z; v.w += u.w;
            }
        }
        *(float4*)&As[m][k4 * 4] = v;
    }
    __syncthreads();

    int tx = tid & 15, ty = tid >> 4;
    int m0 = ty * 4, j0 = tx * 4;
    float acc[4][4];
#pragma unroll
    for (int i = 0; i < 4; i++)
#pragma unroll
        for (int j = 0; j < 4; j++) acc[i][j] = 0.f;

#pragma unroll 16
    for (int k = 0; k < 64; k++) {
        float b0 = Ws[k][j0], b1 = Ws[k][j0 + 1], b2 = Ws[k][j0 + 2], b3 = Ws[k][j0 + 3];
#pragma unroll
        for (int i = 0; i < 4; i++) {
            float a = As[m0 + i][k];
            acc[i][0] = fmaf(a, b0, acc[i][0]);
            acc[i][1] = fmaf(a, b1, acc[i][1]);
            acc[i][2] = fmaf(a, b2, acc[i][2]);
            acc[i][3] = fmaf(a, b3, acc[i][3]);
        }
    }
    float bb0 = bias[j0], bb1 = bias[j0 + 1], bb2 = bias[j0 + 2], bb3 = bias[j0 + 3];
#pragma unroll
    for (int i = 0; i < 4; i++) {
        int row = block_row + m0 + i;
        if (row < n) {
            float4 o = make_float4(acc[i][0] + bb0, acc[i][1] + bb1,
                                   acc[i][2] + bb2, acc[i][3] + bb3);
            ((float4*)Cm)[row * 16 + (j0 >> 2)] = o;
            __half2 p0 = __floats2half2_rn(o.x, o.y);
            __half2 p1 = __floats2half2_rn(o.z, o.w);
            uint2 packed = make_uint2(*(unsigned int*)&p0, *(unsigned int*)&p1);
            ((uint2*)Ch)[row * 16 + (j0 >> 2)] = packed;
        }
    }
}

// ---------------- decoder + log-softmax ----------------
__global__ void decoder_kernel(const float* __restrict__ dw,
                               const float* __restrict__ db,
                               float* __restrict__ out, int n) {
    __shared__ float Ws[HH * CC];
    __shared__ float bs[CC];
    int tid = threadIdx.x;
    for (int i = tid; i < HH * CC; i += blockDim.x) Ws[i] = dw[i];
    if (tid < CC) bs[tid] = db[tid];
    __syncthreads();
    int node = blockIdx.x * blockDim.x + tid;
    if (node >= n) return;
    float acc[CC];
#pragma unroll
    for (int c = 0; c < CC; c++) acc[c] = bs[c];
    const float4* hp = (const float4*)(g_h + node * HH);
#pragma unroll
    for (int k4 = 0; k4 < 16; k4++) {
        float4 v = hp[k4];
        int kb = k4 * 4;
#pragma unroll
        for (int c = 0; c < CC; c++)
            acc[c] += v.x * Ws[(kb + 0) * CC + c] + v.y * Ws[(kb + 1) * CC + c] +
                      v.z * Ws[(kb + 2) * CC + c] + v.w * Ws[(kb + 3) * CC + c];
    }
    float mx = acc[0];
#pragma unroll
    for (int c = 1; c < CC; c++) mx = fmaxf(mx, acc[c]);
    float s = 0.f;
#pragma unroll
    for (int c = 0; c < CC; c++) s += expf(acc[c] - mx);
    float lse = mx + logf(s);
#pragma unroll
    for (int c = 0; c < CC; c++) out[node * CC + c] = acc[c] - lse;
}

// ---------------- launch ----------------
extern "C" void kernel_launch(void* const* d_in, const int* in_sizes, int n_in,
                              void* d_out, int out_size) {
    const float* x      = (const float*)d_in[0];
    const void*  ei     = d_in[1];
    const float* enc_w  = (const float*)d_in[3];
    const float* enc_b  = (const float*)d_in[4];
    const float* proc_w = (const float*)d_in[5];
    const float* proc_b = (const float*)d_in[6];
    const float* dec_w  = (const float*)d_in[7];
    const float* dec_b  = (const float*)d_in[8];
    float* out = (float*)d_out;

    float* hptr = nullptr;
    float* aggptr = nullptr;
    unsigned int* hhptr = nullptr;
    cudaGetSymbolAddress((void**)&hptr, g_h);
    cudaGetSymbolAddress((void**)&aggptr, g_agg);
    cudaGetSymbolAddress((void**)&hhptr, g_hh);

    const int n = NN;

    // fork: encoder GEMM runs concurrently with CSR build
    cudaStream_t s2;
    cudaStreamCreateWithFlags(&s2, cudaStreamNonBlocking);
    cudaEvent_t e0, e1;
    cudaEventCreateWithFlags(&e0, cudaEventDisableTiming);
    cudaEventCreateWithFlags(&e1, cudaEventDisableTiming);
    cudaEventRecord(e0, 0);
    cudaStreamWaitEvent(s2, e0, 0);

    // encoder on s2 (emits fp32 h + fp16 shadow)
    gemm64_kernel<false><<<(n + 63) / 64, 256, 0, s2>>>(x, nullptr, enc_w, enc_b,
                                                        hptr, hhptr, n);
    cudaEventRecord(e1, s2);

    // CSR build on capture stream
    zerodetect_kernel<<<(NN + 255) / 256, 256>>>((const unsigned int*)ei);
    convert_kernel<<<(EE + 255) / 256, 256>>>(ei);
    scan_phase1<<<SCAN_NBLK, SCAN_BLK>>>();
    scan_phase2<<<1, 128>>>();
    scan_phase3<<<SCAN_NBLK, SCAN_BLK>>>();
    scatter_kernel<<<(EE + 255) / 256, 256>>>(ei);

    // join: need both CSR and encoder before first segmax
    cudaStreamWaitEvent(0, e1, 0);

    // 6 GIN layers (segmax: 2 nodes per warp)
    for (int it = 0; it < 6; it++) {
        segmax_kernel<<<((NN / 2) * 32 + 255) / 256, 256>>>();
        gemm64_kernel<true><<<(n + 63) / 64, 256>>>(hptr, aggptr, proc_w, proc_b,
                                                    hptr, hhptr, n);
    }

    // decoder + log-softmax
    decoder_kernel<<<(n + 127) / 128, 128>>>(dec_w, dec_b, out, n);
}